// round 1
// baseline (speedup 1.0000x reference)
#include <cuda_runtime.h>

// LIF timestep, elementwise over N = 16*56*56*256 = 12,845,056 elements.
// Inputs (metadata order): impulse, mem, mem_acc, refrac_until, spikecounts
// Output: 6 stacked planes of N floats:
//   [spikes, mem_out, mem_acc_out, refrac_out, counts_out, spiketrain]
//
// Constants from the reference:
//   V_THRESH = 1.0, DT = 1.0, TAU_REFRAC = 2.0, TIME = 0.5

#define V_THRESH 1.0f
#define TIME_C 0.5f
#define REFRAC_SET 2.5f   // TIME + TAU_REFRAC

__global__ void __launch_bounds__(256, 8)
spike_layer_kernel(const float4* __restrict__ impulse,
                   const float4* __restrict__ mem,
                   const float4* __restrict__ mem_acc,
                   const float4* __restrict__ refrac_until,
                   const float4* __restrict__ spikecounts,
                   float4* __restrict__ out,   // 6 planes of n4 float4 each
                   int n4) {
    int i = blockIdx.x * blockDim.x + threadIdx.x;
    if (i >= n4) return;

    // Front-batch all 5 loads (MLP = 5, overlap DRAM latency)
    const float4 imp = __ldg(&impulse[i]);
    const float4 m   = __ldg(&mem[i]);
    const float4 ma  = __ldg(&mem_acc[i]);
    const float4 ru  = __ldg(&refrac_until[i]);
    const float4 sc  = __ldg(&spikecounts[i]);

    float4 o_spk, o_mem, o_acc, o_ref, o_cnt, o_trn;

    #pragma unroll
    for (int l = 0; l < 4; ++l) {
        const float impv = (&imp.x)[l];
        const float memv = (&m.x)[l];
        const float accv = (&ma.x)[l];
        const float ruv  = (&ru.x)[l];
        const float scv  = (&sc.x)[l];

        // refractory mask on input
        const float masked  = (ruv > TIME_C) ? 0.0f : impv;
        const float new_mem = memv + masked;
        const float new_acc = accv + masked;

        // linear activation: spikes in {0, V_THRESH}
        const bool  fired  = (new_mem >= V_THRESH);
        const float spikes = fired ? V_THRESH : 0.0f;

        // reset by subtraction (spikes<0 branch is unreachable: spikes>=0)
        const float mem_out = fired ? (new_mem - V_THRESH) : new_mem;
        const float ref_out = fired ? REFRAC_SET : ruv;
        const float cnt_out = scv + (fired ? 1.0f : 0.0f);
        const float trn_out = spikes * TIME_C;

        (&o_spk.x)[l] = spikes;
        (&o_mem.x)[l] = mem_out;
        (&o_acc.x)[l] = new_acc;
        (&o_ref.x)[l] = ref_out;
        (&o_cnt.x)[l] = cnt_out;
        (&o_trn.x)[l] = trn_out;
    }

    // 6 output planes, each n4 float4 apart
    out[0 * (size_t)n4 + i] = o_spk;
    out[1 * (size_t)n4 + i] = o_mem;
    out[2 * (size_t)n4 + i] = o_acc;
    out[3 * (size_t)n4 + i] = o_ref;
    out[4 * (size_t)n4 + i] = o_cnt;
    out[5 * (size_t)n4 + i] = o_trn;
}

extern "C" void kernel_launch(void* const* d_in, const int* in_sizes, int n_in,
                              void* d_out, int out_size) {
    const float4* impulse      = (const float4*)d_in[0];
    const float4* mem          = (const float4*)d_in[1];
    const float4* mem_acc      = (const float4*)d_in[2];
    const float4* refrac_until = (const float4*)d_in[3];
    const float4* spikecounts  = (const float4*)d_in[4];
    float4* out = (float4*)d_out;

    const int n  = in_sizes[0];       // 12,845,056 (divisible by 4)
    const int n4 = n / 4;             // 3,211,264

    const int threads = 256;
    const int blocks  = (n4 + threads - 1) / threads;
    spike_layer_kernel<<<blocks, threads>>>(impulse, mem, mem_acc,
                                            refrac_until, spikecounts,
                                            out, n4);
}